// round 15
// baseline (speedup 1.0000x reference)
#include <cuda_runtime.h>
#include <stdint.h>

// Problem shape (fixed by the dataset): B=1, N=100000, E=3200000, H=8, D=64
#define NN 100000
#define HH 8
#define DD 64
#define EE 3200000
#define TOT (EE*HH)          // 25,600,000 outputs
#define NWORDS (TOT/32)      // 800,000 packed mask words

#define DOTS_GRID 1184
#define DOTS_UN 4
#define MASK_GRID 1184
#define MASK_WARPS (MASK_GRID*8)

// Scratch (static device arrays). 16B-aligned for vec I/O.
__device__ __align__(16) float    g_a_self[NN*HH];
__device__ __align__(16) float    g_a_adjc[NN*HH];
__device__ __align__(16) unsigned g_M[NN*HH];     // order-encoded per-(target,head) max
__device__ __align__(16) float    g_P[NN*HH*2];   // packed per (t,half): {as[4], Q[4]}
__device__ __align__(16) unsigned g_mask[NWORDS]; // packed keep bits

// ---------------------------------------------------------------------------
// Threefry-2x32 (20 rounds), key=(0,42), ctr=(0,j), JAX partitionable:
//   bits(j) = x0 ^ x1 ;  keep(j) = bit31 == 0.
// Adds on IMAD (fma pipe) via mad.lo with opaque 'one'; alu pipe carries only
// SHF+LOP3 (40 warp-ops/eval). (R14's mul.wide variant regressed — reverted.)
// ---------------------------------------------------------------------------
__device__ __forceinline__ unsigned addm(unsigned a, unsigned one, unsigned b) {
  unsigned d;
  asm("mad.lo.u32 %0, %1, %2, %3;" : "=r"(d) : "r"(a), "r"(one), "r"(b));
  return d;
}
__device__ __forceinline__ unsigned tf_xor(unsigned j, unsigned one) {
  const unsigned K1  = 42u;
  const unsigned KS2 = 0x1BD11BDAu ^ 42u;
  unsigned x0 = 0u;                 // c0(=0) + ks0(=0)
  unsigned x1 = addm(j, one, K1);   // c1 + ks1
#define TF_R(r) { x0 = addm(x1, one, x0); x1 = __funnelshift_l(x1, x1, (r)); x1 ^= x0; }
  TF_R(13) TF_R(15) TF_R(26) TF_R(6)
  x0 = addm(one, K1, x0);   x1 = addm(one, KS2 + 1u, x1);
  TF_R(17) TF_R(29) TF_R(16) TF_R(24)
  x0 = addm(one, KS2, x0);  x1 = addm(one, 2u, x1);
  TF_R(13) TF_R(15) TF_R(26) TF_R(6)
  /* ks0 = 0 */             x1 = addm(one, K1 + 3u, x1);
  TF_R(17) TF_R(29) TF_R(16) TF_R(24)
  x0 = addm(one, K1, x0);   x1 = addm(one, KS2 + 4u, x1);
  TF_R(13) TF_R(15) TF_R(26) TF_R(6)
  x0 = addm(one, KS2, x0);  x1 = addm(one, 5u, x1);
#undef TF_R
  return x0 ^ x1;
}

// Order-preserving float<->uint encoding for atomicMax
__device__ __forceinline__ unsigned enc_f(float f) {
  unsigned u = __float_as_uint(f);
  return (u & 0x80000000u) ? ~u : (u | 0x80000000u);
}
__device__ __forceinline__ float dec_f(unsigned k) {
  unsigned u = (k & 0x80000000u) ? (k ^ 0x80000000u) : ~k;
  return __uint_as_float(u);
}
__device__ __forceinline__ float leaky(float x) {
  return fmaxf(x, 0.2f * x);
}

// ---------------------------------------------------------------------------
// MASK (parallel graph branch): pure threefry, 4 words/warp-iter for ILP.
// Runs concurrently with the dots->em->prep chain on a forked stream.
// ---------------------------------------------------------------------------
__global__ void k_mask(unsigned one) {
  unsigned lane  = threadIdx.x & 31u;
  unsigned mwarp = (blockIdx.x * blockDim.x + threadIdx.x) >> 5;
  for (unsigned w = 4u*mwarp; w < (unsigned)NWORDS; w += 4u*MASK_WARPS) {
    unsigned j = w * 32u + lane;
    unsigned b0 = tf_xor(j,        one);
    unsigned b1 = tf_xor(j + 32u,  one);
    unsigned b2 = tf_xor(j + 64u,  one);
    unsigned b3 = tf_xor(j + 96u,  one);
    unsigned w0 = __ballot_sync(0xFFFFFFFFu, (b0 & 0x80000000u) == 0u);
    unsigned w1 = __ballot_sync(0xFFFFFFFFu, (b1 & 0x80000000u) == 0u);
    unsigned w2 = __ballot_sync(0xFFFFFFFFu, (b2 & 0x80000000u) == 0u);
    unsigned w3 = __ballot_sync(0xFFFFFFFFu, (b3 & 0x80000000u) == 0u);
    if (lane == 0)
      *reinterpret_cast<uint4*>(g_mask + w) = make_uint4(w0, w1, w2, w3);
  }
}

// ---------------------------------------------------------------------------
// K1: dots via float4 loads (R13). Warp covers two head-rows of one node.
// ---------------------------------------------------------------------------
__global__ void k_dots(const float* __restrict__ X,
                       const float* __restrict__ Ws,
                       const float* __restrict__ Wa) {
  int w  = threadIdx.x >> 5;
  int l  = threadIdx.x & 31;
  int no = w >> 2;
  int p  = w & 3;
  int hh = 2*p + (l >> 4);
  int db = (l & 15) * 4;

  float ws0 = Ws[(db    )*HH + hh], ws1 = Ws[(db + 1)*HH + hh];
  float ws2 = Ws[(db + 2)*HH + hh], ws3 = Ws[(db + 3)*HH + hh];
  float wa0 = Wa[(db    )*HH + hh], wa1 = Wa[(db + 1)*HH + hh];
  float wa2 = Wa[(db + 2)*HH + hh], wa3 = Wa[(db + 3)*HH + hh];

  const int STRIDE = DOTS_GRID * 2 * DOTS_UN;
  for (int n0 = blockIdx.x * 2 * DOTS_UN; n0 < NN; n0 += STRIDE) {
    float4 x[DOTS_UN];
    int n[DOTS_UN];
#pragma unroll
    for (int u = 0; u < DOTS_UN; u++) {
      n[u] = n0 + 2*u + no;
      if (n[u] < NN)
        x[u] = *reinterpret_cast<const float4*>(
            X + (size_t)n[u]*512 + hh*64 + db);
    }
#pragma unroll
    for (int u = 0; u < DOTS_UN; u++) {
      if (n[u] < NN) {
        float ds = x[u].x*ws0 + x[u].y*ws1 + x[u].z*ws2 + x[u].w*ws3;
        float da = x[u].x*wa0 + x[u].y*wa1 + x[u].z*wa2 + x[u].w*wa3;
#pragma unroll
        for (int o = 8; o; o >>= 1) {
          ds += __shfl_down_sync(0xFFFFFFFFu, ds, o);
          da += __shfl_down_sync(0xFFFFFFFFu, da, o);
        }
        if ((l & 15) == 0) {
          g_a_self[n[u]*HH + hh] = ds;
          g_a_adjc[n[u]*HH + hh] = da;
          g_M[n[u]*HH + hh] = 0u;
        }
      }
    }
  }
}

// ---------------------------------------------------------------------------
// K2: segment max, 1 edge/thread, filtered atomics (R13). Stale reads safe.
// ---------------------------------------------------------------------------
__global__ void k_em(const int* __restrict__ targets,
                     const int* __restrict__ sources) {
  int e = blockIdx.x * blockDim.x + threadIdx.x;
  if (e >= EE) return;
  int t = targets[e];
  int s = sources[e];
  const float4 a0 = *reinterpret_cast<const float4*>(g_a_adjc + s*8);
  const float4 a1 = *reinterpret_cast<const float4*>(g_a_adjc + s*8 + 4);
  const uint4  m0 = *reinterpret_cast<const uint4 *>(g_M + t*8);
  const uint4  m1 = *reinterpret_cast<const uint4 *>(g_M + t*8 + 4);
  unsigned v;
  v = enc_f(a0.x); if (v > m0.x) atomicMax(&g_M[t*8 + 0], v);
  v = enc_f(a0.y); if (v > m0.y) atomicMax(&g_M[t*8 + 1], v);
  v = enc_f(a0.z); if (v > m0.z) atomicMax(&g_M[t*8 + 2], v);
  v = enc_f(a0.w); if (v > m0.w) atomicMax(&g_M[t*8 + 3], v);
  v = enc_f(a1.x); if (v > m1.x) atomicMax(&g_M[t*8 + 4], v);
  v = enc_f(a1.y); if (v > m1.y) atomicMax(&g_M[t*8 + 5], v);
  v = enc_f(a1.z); if (v > m1.z) atomicMax(&g_M[t*8 + 6], v);
  v = enc_f(a1.w); if (v > m1.w) atomicMax(&g_M[t*8 + 7], v);
}

// ---------------------------------------------------------------------------
// K3: pack P[t,half] = {as[h..h+3], Q[h..h+3]},  Q = 2*exp(-leaky(as + max)).
// ---------------------------------------------------------------------------
__global__ void k_prep() {
  int i = blockIdx.x * blockDim.x + threadIdx.x;    // over NN*2
  if (i >= NN*2) return;
  int base = i * 4;
  float4 as = *reinterpret_cast<const float4*>(g_a_self + base);
  uint4  me = *reinterpret_cast<const uint4 *>(g_M     + base);
  float4 q;
  q.x = 2.0f * __expf(-leaky(as.x + dec_f(me.x)));
  q.y = 2.0f * __expf(-leaky(as.y + dec_f(me.y)));
  q.z = 2.0f * __expf(-leaky(as.z + dec_f(me.z)));
  q.w = 2.0f * __expf(-leaky(as.w + dec_f(me.w)));
  *reinterpret_cast<float4*>(g_P + i*8)     = as;
  *reinterpret_cast<float4*>(g_P + i*8 + 4) = q;
}

// ---------------------------------------------------------------------------
// K4: 4 outputs/thread, mask precomputed -> pure memory kernel.
//   out[j] = keepbit ? Q[t,h] * exp(leaky(as[t,h] + aa[s,h])) : 0
// Gathers: P (1 line), aa4 (1 line), mask word (coalesced).
// ---------------------------------------------------------------------------
__global__ void k_out(const int* __restrict__ targets,
                      const int* __restrict__ sources,
                      float* __restrict__ out) {
  unsigned tI = blockIdx.x * blockDim.x + threadIdx.x;  // 0 .. TOT/4-1
  if (tI >= (unsigned)(TOT/4)) return;
  unsigned j0   = 4u * tI;
  unsigned e    = tI >> 1;
  unsigned half = tI & 1u;
  unsigned h    = half * 4u;

  unsigned word = g_mask[j0 >> 5];
  unsigned b = word >> (j0 & 31u);

  int t = targets[e];
  int s = sources[e];
  const float* pb = g_P + ((unsigned)t*2u + half)*8u;
  float4 as = *reinterpret_cast<const float4*>(pb);
  float4 q  = *reinterpret_cast<const float4*>(pb + 4);
  float4 aa = *reinterpret_cast<const float4*>(g_a_adjc + (unsigned)s*8u + h);

  float4 o;
  o.x = (b & 1u) ? q.x * __expf(leaky(as.x + aa.x)) : 0.0f;
  o.y = (b & 2u) ? q.y * __expf(leaky(as.y + aa.y)) : 0.0f;
  o.z = (b & 4u) ? q.z * __expf(leaky(as.z + aa.z)) : 0.0f;
  o.w = (b & 8u) ? q.w * __expf(leaky(as.w + aa.w)) : 0.0f;
  *reinterpret_cast<float4*>(out + j0) = o;
}

// ---------------------------------------------------------------------------
extern "C" void kernel_launch(void* const* d_in, const int* in_sizes, int n_in,
                              void* d_out, int out_size) {
  const float* X  = (const float*)d_in[0];
  const float* Ws = (const float*)d_in[1];
  const float* Wa = (const float*)d_in[2];
  // input order: X, Wself, Wadjc, [N scalar], targets, sources, degree
  int ti = (n_in >= 6 && in_sizes[3] == 1) ? 4 : 3;
  const int* targets = (const int*)d_in[ti];
  const int* sources = (const int*)d_in[ti + 1];
  float* out = (float*)d_out;

  // One-time infra (host objects only; no device memory). Same work every call.
  static cudaStream_t s2 = nullptr;
  static cudaEvent_t  evF = nullptr, evJ = nullptr;
  if (s2 == nullptr) {
    cudaStreamCreateWithFlags(&s2, cudaStreamNonBlocking);
    cudaEventCreateWithFlags(&evF, cudaEventDisableTiming);
    cudaEventCreateWithFlags(&evJ, cudaEventDisableTiming);
  }

  // Fork: mask branch runs concurrently with the dots->em->prep chain.
  cudaEventRecord(evF, 0);
  cudaStreamWaitEvent(s2, evF, 0);
  k_mask<<<MASK_GRID, 256, 0, s2>>>(1u);
  cudaEventRecord(evJ, s2);

  k_dots<<<DOTS_GRID, 256>>>(X, Ws, Wa);
  k_em  <<<(EE + 255) / 256, 256>>>(targets, sources);
  k_prep<<<(NN*2 + 255) / 256, 256>>>();

  // Join, then the output kernel consumes both branches.
  cudaStreamWaitEvent(0, evJ, 0);
  k_out<<<(TOT/4 + 255) / 256, 256>>>(targets, sources, out);
}

// round 16
// speedup vs baseline: 1.1805x; 1.1805x over previous
#include <cuda_runtime.h>
#include <stdint.h>

// Problem shape (fixed by the dataset): B=1, N=100000, E=3200000, H=8, D=64
#define NN 100000
#define HH 8
#define DD 64
#define EE 3200000
#define TOT (EE*HH)          // 25,600,000 outputs

#define DOTS_GRID 1184
#define DOTS_UN 4

// Scratch (static device arrays). 16B-aligned for vec I/O.
__device__ __align__(16) float    g_a_self[NN*HH];
__device__ __align__(16) float    g_a_adjc[NN*HH];
__device__ __align__(16) unsigned g_M[NN*HH];    // order-encoded per-(target,head) max
__device__ __align__(16) float    g_P[NN*HH*2];  // per node: {as[0..3],Q[0..3],as[4..7],Q[4..7]}

// ---------------------------------------------------------------------------
// Threefry-2x32 (20 rounds), key=(0,42), ctr=(0,j), JAX partitionable:
//   bits(j) = x0 ^ x1 ;  keep(j) = bit31 == 0.
// Adds on IMAD (fma pipe) via mad.lo with opaque 'one'; alu pipe carries only
// SHF+LOP3 (40 warp-ops/eval). This inline-in-k_out schedule is the only mask
// schedule that measured faster than serial (R13: 74.6us for mask+output).
// ---------------------------------------------------------------------------
__device__ __forceinline__ unsigned addm(unsigned a, unsigned one, unsigned b) {
  unsigned d;
  asm("mad.lo.u32 %0, %1, %2, %3;" : "=r"(d) : "r"(a), "r"(one), "r"(b));
  return d;
}
__device__ __forceinline__ unsigned tf_xor(unsigned j, unsigned one) {
  const unsigned K1  = 42u;
  const unsigned KS2 = 0x1BD11BDAu ^ 42u;
  unsigned x0 = 0u;                 // c0(=0) + ks0(=0)
  unsigned x1 = addm(j, one, K1);   // c1 + ks1
#define TF_R(r) { x0 = addm(x1, one, x0); x1 = __funnelshift_l(x1, x1, (r)); x1 ^= x0; }
  TF_R(13) TF_R(15) TF_R(26) TF_R(6)
  x0 = addm(one, K1, x0);   x1 = addm(one, KS2 + 1u, x1);
  TF_R(17) TF_R(29) TF_R(16) TF_R(24)
  x0 = addm(one, KS2, x0);  x1 = addm(one, 2u, x1);
  TF_R(13) TF_R(15) TF_R(26) TF_R(6)
  /* ks0 = 0 */             x1 = addm(one, K1 + 3u, x1);
  TF_R(17) TF_R(29) TF_R(16) TF_R(24)
  x0 = addm(one, K1, x0);   x1 = addm(one, KS2 + 4u, x1);
  TF_R(13) TF_R(15) TF_R(26) TF_R(6)
  x0 = addm(one, KS2, x0);  x1 = addm(one, 5u, x1);
#undef TF_R
  return x0 ^ x1;
}

// Order-preserving float<->uint encoding for atomicMax
__device__ __forceinline__ unsigned enc_f(float f) {
  unsigned u = __float_as_uint(f);
  return (u & 0x80000000u) ? ~u : (u | 0x80000000u);
}
__device__ __forceinline__ float dec_f(unsigned k) {
  unsigned u = (k & 0x80000000u) ? (k ^ 0x80000000u) : ~k;
  return __uint_as_float(u);
}
__device__ __forceinline__ float leaky(float x) {
  return fmaxf(x, 0.2f * x);
}

// ---------------------------------------------------------------------------
// K1: dots via float4 loads (R13). Warp covers two head-rows of one node:
//   lane 0-15 -> head 2p, lane 16-31 -> head 2p+1; one LDG.128/lane.
// 16-lane shfl reduction; lanes 0/16 write. g_M zero-init folded in.
// ---------------------------------------------------------------------------
__global__ void k_dots(const float* __restrict__ X,
                       const float* __restrict__ Ws,
                       const float* __restrict__ Wa) {
  int w  = threadIdx.x >> 5;
  int l  = threadIdx.x & 31;
  int no = w >> 2;
  int p  = w & 3;
  int hh = 2*p + (l >> 4);
  int db = (l & 15) * 4;

  float ws0 = Ws[(db    )*HH + hh], ws1 = Ws[(db + 1)*HH + hh];
  float ws2 = Ws[(db + 2)*HH + hh], ws3 = Ws[(db + 3)*HH + hh];
  float wa0 = Wa[(db    )*HH + hh], wa1 = Wa[(db + 1)*HH + hh];
  float wa2 = Wa[(db + 2)*HH + hh], wa3 = Wa[(db + 3)*HH + hh];

  const int STRIDE = DOTS_GRID * 2 * DOTS_UN;
  for (int n0 = blockIdx.x * 2 * DOTS_UN; n0 < NN; n0 += STRIDE) {
    float4 x[DOTS_UN];
    int n[DOTS_UN];
#pragma unroll
    for (int u = 0; u < DOTS_UN; u++) {
      n[u] = n0 + 2*u + no;
      if (n[u] < NN)
        x[u] = *reinterpret_cast<const float4*>(
            X + (size_t)n[u]*512 + hh*64 + db);
    }
#pragma unroll
    for (int u = 0; u < DOTS_UN; u++) {
      if (n[u] < NN) {
        float ds = x[u].x*ws0 + x[u].y*ws1 + x[u].z*ws2 + x[u].w*ws3;
        float da = x[u].x*wa0 + x[u].y*wa1 + x[u].z*wa2 + x[u].w*wa3;
#pragma unroll
        for (int o = 8; o; o >>= 1) {
          ds += __shfl_down_sync(0xFFFFFFFFu, ds, o);
          da += __shfl_down_sync(0xFFFFFFFFu, da, o);
        }
        if ((l & 15) == 0) {
          g_a_self[n[u]*HH + hh] = ds;
          g_a_adjc[n[u]*HH + hh] = da;
          g_M[n[u]*HH + hh] = 0u;
        }
      }
    }
  }
}

// ---------------------------------------------------------------------------
// K2: segment max, 1 edge/thread, filtered atomics (R13). Stale reads safe
// (M only grows -> at worst a redundant atomic).
// ---------------------------------------------------------------------------
__global__ void k_em(const int* __restrict__ targets,
                     const int* __restrict__ sources) {
  int e = blockIdx.x * blockDim.x + threadIdx.x;
  if (e >= EE) return;
  int t = targets[e];
  int s = sources[e];
  const float4 a0 = *reinterpret_cast<const float4*>(g_a_adjc + s*8);
  const float4 a1 = *reinterpret_cast<const float4*>(g_a_adjc + s*8 + 4);
  const uint4  m0 = *reinterpret_cast<const uint4 *>(g_M + t*8);
  const uint4  m1 = *reinterpret_cast<const uint4 *>(g_M + t*8 + 4);
  unsigned v;
  v = enc_f(a0.x); if (v > m0.x) atomicMax(&g_M[t*8 + 0], v);
  v = enc_f(a0.y); if (v > m0.y) atomicMax(&g_M[t*8 + 1], v);
  v = enc_f(a0.z); if (v > m0.z) atomicMax(&g_M[t*8 + 2], v);
  v = enc_f(a0.w); if (v > m0.w) atomicMax(&g_M[t*8 + 3], v);
  v = enc_f(a1.x); if (v > m1.x) atomicMax(&g_M[t*8 + 4], v);
  v = enc_f(a1.y); if (v > m1.y) atomicMax(&g_M[t*8 + 5], v);
  v = enc_f(a1.z); if (v > m1.z) atomicMax(&g_M[t*8 + 6], v);
  v = enc_f(a1.w); if (v > m1.w) atomicMax(&g_M[t*8 + 7], v);
}

// ---------------------------------------------------------------------------
// K3: pack P: per (node,half) {as[4], Q[4]},  Q = 2*exp(-leaky(as + max)).
// ---------------------------------------------------------------------------
__global__ void k_prep() {
  int i = blockIdx.x * blockDim.x + threadIdx.x;    // over NN*2
  if (i >= NN*2) return;
  int base = i * 4;
  float4 as = *reinterpret_cast<const float4*>(g_a_self + base);
  uint4  me = *reinterpret_cast<const uint4 *>(g_M     + base);
  float4 q;
  q.x = 2.0f * __expf(-leaky(as.x + dec_f(me.x)));
  q.y = 2.0f * __expf(-leaky(as.y + dec_f(me.y)));
  q.z = 2.0f * __expf(-leaky(as.z + dec_f(me.z)));
  q.w = 2.0f * __expf(-leaky(as.w + dec_f(me.w)));
  *reinterpret_cast<float4*>(g_P + i*8)     = as;
  *reinterpret_cast<float4*>(g_P + i*8 + 4) = q;
}

// ---------------------------------------------------------------------------
// K4: 8 outputs/thread (one full edge), threefry inline.
//   out[e,h] = keep(e*8+h) ? Q[t,h] * exp(leaky(as[t,h] + aa[s,h])) : 0
// Loads per edge: t,s (coalesced), P[t] 64B (64B-aligned -> ONE 128B line),
// aa 32B (1 line); 2 coalesced STG.128. Threefry alu fills the gather stalls.
// ---------------------------------------------------------------------------
__global__ void k_out(const int* __restrict__ targets,
                      const int* __restrict__ sources,
                      float* __restrict__ out, unsigned one) {
  unsigned e = blockIdx.x * blockDim.x + threadIdx.x;
  if (e >= (unsigned)EE) return;
  unsigned j0 = 8u * e;

  int t = targets[e];
  int s = sources[e];
  const float* pb = g_P + (unsigned)t*16u;
  float4 as0 = *reinterpret_cast<const float4*>(pb);
  float4 q0  = *reinterpret_cast<const float4*>(pb + 4);
  float4 as1 = *reinterpret_cast<const float4*>(pb + 8);
  float4 q1  = *reinterpret_cast<const float4*>(pb + 12);
  float4 aa0 = *reinterpret_cast<const float4*>(g_a_adjc + (unsigned)s*8u);
  float4 aa1 = *reinterpret_cast<const float4*>(g_a_adjc + (unsigned)s*8u + 4);

  unsigned b0 = tf_xor(j0,      one);
  unsigned b1 = tf_xor(j0 + 1u, one);
  unsigned b2 = tf_xor(j0 + 2u, one);
  unsigned b3 = tf_xor(j0 + 3u, one);
  unsigned b4 = tf_xor(j0 + 4u, one);
  unsigned b5 = tf_xor(j0 + 5u, one);
  unsigned b6 = tf_xor(j0 + 6u, one);
  unsigned b7 = tf_xor(j0 + 7u, one);

  float4 o0, o1;
  o0.x = (b0 & 0x80000000u) ? 0.0f : q0.x * __expf(leaky(as0.x + aa0.x));
  o0.y = (b1 & 0x80000000u) ? 0.0f : q0.y * __expf(leaky(as0.y + aa0.y));
  o0.z = (b2 & 0x80000000u) ? 0.0f : q0.z * __expf(leaky(as0.z + aa0.z));
  o0.w = (b3 & 0x80000000u) ? 0.0f : q0.w * __expf(leaky(as0.w + aa0.w));
  o1.x = (b4 & 0x80000000u) ? 0.0f : q1.x * __expf(leaky(as1.x + aa1.x));
  o1.y = (b5 & 0x80000000u) ? 0.0f : q1.y * __expf(leaky(as1.y + aa1.y));
  o1.z = (b6 & 0x80000000u) ? 0.0f : q1.z * __expf(leaky(as1.z + aa1.z));
  o1.w = (b7 & 0x80000000u) ? 0.0f : q1.w * __expf(leaky(as1.w + aa1.w));
  *reinterpret_cast<float4*>(out + j0)      = o0;
  *reinterpret_cast<float4*>(out + j0 + 4u) = o1;
}

// ---------------------------------------------------------------------------
extern "C" void kernel_launch(void* const* d_in, const int* in_sizes, int n_in,
                              void* d_out, int out_size) {
  const float* X  = (const float*)d_in[0];
  const float* Ws = (const float*)d_in[1];
  const float* Wa = (const float*)d_in[2];
  // input order: X, Wself, Wadjc, [N scalar], targets, sources, degree
  int ti = (n_in >= 6 && in_sizes[3] == 1) ? 4 : 3;
  const int* targets = (const int*)d_in[ti];
  const int* sources = (const int*)d_in[ti + 1];
  float* out = (float*)d_out;

  k_dots<<<DOTS_GRID, 256>>>(X, Ws, Wa);
  k_em  <<<(EE + 255) / 256, 256>>>(targets, sources);
  k_prep<<<(NN*2 + 255) / 256, 256>>>();
  k_out <<<(EE + 255) / 256, 256>>>(targets, sources, out, 1u);
}